// round 4
// baseline (speedup 1.0000x reference)
#include <cuda_runtime.h>
#include <stdint.h>

// Problem constants
#define N_V   16384
#define N_E   8192
#define CIN   128
#define COUT  64
#define LOG_M 13

// Persistent-kernel config: 4 blocks/SM x 148 SMs -> residency guaranteed
// (__launch_bounds__(256,4) caps regs at 64; smem 4KB/block)
#define GRID   592
#define BLOCK  256
#define NTH    (GRID*BLOCK)        // 151552
#define NWARP  (NTH/32)            // 4736
#define GEMMB  64                  // blocks [0,64) do GEMM during phase 1
#define EXB    (GRID-GEMMB)        // 528 extract blocks
#define ENTH   (EXB*BLOCK)         // 135168 extract threads
#define CAPB   2048                // COO slots per extract block (mean ~1271, sigma ~36)
#define LOG_CAPB 11
#define TOT4   (N_V*(N_E/4))       // 33,554,432 uint4 elements of H

// ---------------- device scratch (no allocation) ----------------
__device__ unsigned g_bar[8];                 // monotonic barrier tickets (never reset)
__device__ int      g_deg_v[N_V], g_deg_e[N_E];
__device__ int      g_cur_v[N_V], g_cur_e[N_E];
__device__ int      g_off_v[N_V + 1], g_off_e[N_E + 1];
__device__ int      g_blk_cnt[EXB];
__device__ unsigned g_coo[EXB * CAPB];        // packed (i<<13)|j
__device__ int      g_adj_v[EXB * CAPB];      // CSR by vertex: edge ids
__device__ int      g_adj_e[EXB * CAPB];      // CSC by edge: vertex ids
__device__ float    g_dv[N_V], g_de[N_E];
__device__ float    g_Z[N_V * COUT];          // X @ W^T + b  (dv folded later)
__device__ float    g_Y2[N_E * COUT];         // de * (H^T @ (dv.Z))

// ---------------- grid barrier: monotonic tickets, replay-safe ----------------
__device__ __forceinline__ void gsync(int b) {
    __syncthreads();
    __threadfence();                                   // release all threads' writes
    __syncthreads();
    if (threadIdx.x == 0) {
        unsigned old = atomicAdd(&g_bar[b], 1u);
        unsigned target = old - (old % GRID) + GRID;   // this launch's completion count
        unsigned cur;
        for (;;) {
            asm volatile("ld.acquire.gpu.u32 %0, [%1];" : "=r"(cur) : "l"(&g_bar[b]));
            if (cur >= target) break;
            __nanosleep(128);
        }
    }
    __syncthreads();
}

// ---------------- extract helpers ----------------
__device__ __forceinline__ void emit(unsigned hv, int e, int* s_cnt, unsigned cooBase) {
    if (hv) {
        int i = e >> LOG_M;
        int j = e & (N_E - 1);
        atomicAdd(&g_deg_v[i], 1);
        atomicAdd(&g_deg_e[j], 1);
        int p = atomicAdd(s_cnt, 1);                   // shared atomic: cheap
        if (p < CAPB)
            g_coo[cooBase + p] = ((unsigned)i << LOG_M) | (unsigned)j;
    }
}

__device__ __forceinline__ void proc4(uint4 h, int v, int* s_cnt, unsigned cooBase) {
    if ((h.x | h.y | h.z | h.w) == 0u) return;         // ~98% of vectors
    int e = v * 4;
    emit(h.x, e,     s_cnt, cooBase);
    emit(h.y, e + 1, s_cnt, cooBase);
    emit(h.z, e + 2, s_cnt, cooBase);
    emit(h.w, e + 3, s_cnt, cooBase);
}

// ---------------- scan + scales (single block, 256 threads) ----------------
__device__ void scan_scale(int n, int per, int* deg, int* off, float* sc,
                           bool isV, int* part) {
    int tid = threadIdx.x;
    int base = tid * per;
    int s = 0;
    for (int k = 0; k < per; k++) s += __ldcg(&deg[base + k]);
    part[tid] = s;
    __syncthreads();
    for (int d = 1; d < 256; d <<= 1) {
        int v = (tid >= d) ? part[tid - d] : 0;
        __syncthreads();
        part[tid] += v;
        __syncthreads();
    }
    int pre = tid ? part[tid - 1] : 0;
    for (int k = 0; k < per; k++) {
        int d = __ldcg(&deg[base + k]);
        off[base + k] = pre;
        pre += d;
        sc[base + k] = (d > 0) ? (isV ? rsqrtf((float)d) : 1.0f / (float)d) : 0.0f;
    }
    if (tid == 255) off[n] = pre;
}

// ---------------- the fused persistent kernel ----------------
__global__ void __launch_bounds__(BLOCK, 4)
fused(const float* __restrict__ X, const float* __restrict__ H,
      const float* __restrict__ W, const float* __restrict__ bias,
      float* __restrict__ out) {
    __shared__ __align__(16) unsigned char sb[4096];   // 4KB: scan part / s_cnt / GEMM row stage
    const int tid  = threadIdx.x;
    const int bx   = blockIdx.x;
    const int gtid = bx * BLOCK + tid;
    const int wid  = tid >> 5;
    const int lane = tid & 31;

    // ============ Phase 1: extract (528 blocks) || GEMM Z0 (64 blocks) ============
    if (bx < GEMMB) {
        // Z0[i][c] = sum_k X[i][k]*W[c][k] + b[c]; warp per row, lane -> cols (lane, lane+32).
        // X row staged in per-warp smem (512B); W rows streamed per-lane (L1-hot, 32KB total).
        float4* srow4 = (float4*)(sb + wid * 512);     // 32 float4 per warp
        const float4* __restrict__ X4 = (const float4*)X;
        const float4* __restrict__ Wc0 = (const float4*)(W + lane * CIN);
        const float4* __restrict__ Wc1 = (const float4*)(W + (lane + 32) * CIN);
        float b0 = bias[lane], b1 = bias[lane + 32];
        int gw = bx * 8 + wid;                         // 0..511
        for (int r = 0; r < 32; r++) {                 // 512 warps x 32 rows = 16384
            int i = gw * 32 + r;
            srow4[lane] = X4[i * 32 + lane];           // 32 float4 = full row
            __syncwarp();
            float a0 = 0.f, a1 = 0.f;
#pragma unroll
            for (int k4 = 0; k4 < 32; k4++) {
                float4 xv = srow4[k4];
                float4 w0 = Wc0[k4];
                float4 w1 = Wc1[k4];
                a0 += xv.x * w0.x + xv.y * w0.y + xv.z * w0.z + xv.w * w0.w;
                a1 += xv.x * w1.x + xv.y * w1.y + xv.z * w1.z + xv.w * w1.w;
            }
            g_Z[i * COUT + lane]      = a0 + b0;
            g_Z[i * COUT + lane + 32] = a1 + b1;
            __syncwarp();                              // srow reuse next row
        }
    } else {
        // streaming extract over H (536 MB), 8-deep load batches (32 regs)
        int* s_cnt = (int*)sb;
        if (tid == 0) *s_cnt = 0;
        __syncthreads();
        int eb = bx - GEMMB;
        unsigned cooBase = (unsigned)eb * CAPB;
        int etid = eb * BLOCK + tid;
        const uint4* __restrict__ H4 = (const uint4*)H;
        int v = etid;
        // 31 batches x 8 strides = 248 strides; max idx = 135167 + 247*135168 < TOT4
        for (int it = 0; it < 31; it++) {
            uint4 r[8];
#pragma unroll
            for (int u = 0; u < 8; u++) r[u] = __ldcs(&H4[v + u * ENTH]);
#pragma unroll
            for (int u = 0; u < 8; u++) proc4(r[u], v + u * ENTH, s_cnt, cooBase);
            v += 8 * ENTH;
        }
        while (v < TOT4) { proc4(__ldcs(&H4[v]), v, s_cnt, cooBase); v += ENTH; }
        __syncthreads();
        if (tid == 0) g_blk_cnt[eb] = (*s_cnt < CAPB) ? *s_cnt : CAPB;
    }
    gsync(0);

    // ============ Phase 2: prefix scans + scales (blocks 0,1) ============
    if (bx == 0)      scan_scale(N_V, 64, g_deg_v, g_off_v, g_dv, true,  (int*)sb);
    else if (bx == 1) scan_scale(N_E, 32, g_deg_e, g_off_e, g_de, false, (int*)sb);
    gsync(1);

    // ============ Phase 3: bucket COO into CSR(vertex) + CSC(edge) ============
    for (int idx = gtid; idx < EXB * CAPB; idx += NTH) {
        int blk = idx >> LOG_CAPB;
        int loc = idx & (CAPB - 1);
        if (loc < __ldcg(&g_blk_cnt[blk])) {
            unsigned p = __ldcg(&g_coo[idx]);
            int i = p >> LOG_M;
            int j = p & (N_E - 1);
            int pv = atomicAdd(&g_cur_v[i], 1);
            g_adj_v[__ldcg(&g_off_v[i]) + pv] = j;
            int pe = atomicAdd(&g_cur_e[j], 1);
            g_adj_e[__ldcg(&g_off_e[j]) + pe] = i;
        }
    }
    gsync(2);

    // ============ Phase 4: Y2[j] = de_j * sum_{i in j} dv_i * Z0[i] ============
    {
        int w = gtid >> 5;
        for (int e = w; e < N_E; e += NWARP) {
            int t = __ldcg(&g_off_e[e]), end = __ldcg(&g_off_e[e + 1]);
            float a0 = 0.f, a1 = 0.f;
            for (; t + 4 <= end; t += 4) {
                int i0 = __ldcg(&g_adj_e[t]);
                int i1 = __ldcg(&g_adj_e[t + 1]);
                int i2 = __ldcg(&g_adj_e[t + 2]);
                int i3 = __ldcg(&g_adj_e[t + 3]);
                float s0 = __ldcg(&g_dv[i0]), s1 = __ldcg(&g_dv[i1]);
                float s2 = __ldcg(&g_dv[i2]), s3 = __ldcg(&g_dv[i3]);
                float z00 = __ldcg(&g_Z[i0 * COUT + lane]);
                float z01 = __ldcg(&g_Z[i0 * COUT + lane + 32]);
                float z10 = __ldcg(&g_Z[i1 * COUT + lane]);
                float z11 = __ldcg(&g_Z[i1 * COUT + lane + 32]);
                float z20 = __ldcg(&g_Z[i2 * COUT + lane]);
                float z21 = __ldcg(&g_Z[i2 * COUT + lane + 32]);
                float z30 = __ldcg(&g_Z[i3 * COUT + lane]);
                float z31 = __ldcg(&g_Z[i3 * COUT + lane + 32]);
                a0 += s0 * z00 + s1 * z10 + s2 * z20 + s3 * z30;
                a1 += s0 * z01 + s1 * z11 + s2 * z21 + s3 * z31;
            }
            for (; t < end; t++) {
                int i0 = __ldcg(&g_adj_e[t]);
                float s0 = __ldcg(&g_dv[i0]);
                a0 += s0 * __ldcg(&g_Z[i0 * COUT + lane]);
                a1 += s0 * __ldcg(&g_Z[i0 * COUT + lane + 32]);
            }
            float de = __ldcg(&g_de[e]);
            g_Y2[e * COUT + lane]      = a0 * de;
            g_Y2[e * COUT + lane + 32] = a1 * de;
        }
    }
    gsync(3);

    // ============ Phase 5: out[i] = relu(dv_i * sum_{j in i} Y2[j]) ============
    {
        int w = gtid >> 5;
        for (int vi = w; vi < N_V; vi += NWARP) {
            int t = __ldcg(&g_off_v[vi]), end = __ldcg(&g_off_v[vi + 1]);
            float a0 = 0.f, a1 = 0.f;
            for (; t + 4 <= end; t += 4) {
                int j0 = __ldcg(&g_adj_v[t]);
                int j1 = __ldcg(&g_adj_v[t + 1]);
                int j2 = __ldcg(&g_adj_v[t + 2]);
                int j3 = __ldcg(&g_adj_v[t + 3]);
                float y00 = __ldcg(&g_Y2[j0 * COUT + lane]);
                float y01 = __ldcg(&g_Y2[j0 * COUT + lane + 32]);
                float y10 = __ldcg(&g_Y2[j1 * COUT + lane]);
                float y11 = __ldcg(&g_Y2[j1 * COUT + lane + 32]);
                float y20 = __ldcg(&g_Y2[j2 * COUT + lane]);
                float y21 = __ldcg(&g_Y2[j2 * COUT + lane + 32]);
                float y30 = __ldcg(&g_Y2[j3 * COUT + lane]);
                float y31 = __ldcg(&g_Y2[j3 * COUT + lane + 32]);
                a0 += y00 + y10 + y20 + y30;
                a1 += y01 + y11 + y21 + y31;
            }
            for (; t < end; t++) {
                int j0 = __ldcg(&g_adj_v[t]);
                a0 += __ldcg(&g_Y2[j0 * COUT + lane]);
                a1 += __ldcg(&g_Y2[j0 * COUT + lane + 32]);
            }
            float dv = __ldcg(&g_dv[vi]);
            float o0 = dv * a0;
            float o1 = dv * a1;
            out[vi * COUT + lane]      = o0 > 0.f ? o0 : 0.f;
            out[vi * COUT + lane + 32] = o1 > 0.f ? o1 : 0.f;
        }
    }

    // ---- tail: re-zero counters for the NEXT launch (replay-safe; launch 0
    // relies on static zero-init of __device__ globals). No reader remains. ----
    for (int k = gtid; k < N_V; k += NTH) { g_deg_v[k] = 0; g_cur_v[k] = 0; }
    for (int k = gtid; k < N_E; k += NTH) { g_deg_e[k] = 0; g_cur_e[k] = 0; }
}

// ---------------- launch ----------------
extern "C" void kernel_launch(void* const* d_in, const int* in_sizes, int n_in,
                              void* d_out, int out_size) {
    const float* X = (const float*)d_in[0];   // (16384, 128)
    const float* H = (const float*)d_in[1];   // (16384, 8192)
    const float* W = (const float*)d_in[2];   // (64, 128)
    const float* b = (const float*)d_in[3];   // (64,)
    float* out = (float*)d_out;               // (16384, 64)

    fused<<<GRID, BLOCK>>>(X, H, W, b, out);
}